// round 1
// baseline (speedup 1.0000x reference)
#include <cuda_runtime.h>

// PatchEmbeder: out[b,0,:] = cls + pos[0];  out[b,p+1,:] = ((x@W1+b1)@W2+b2)@W3+b3 + pos[p+1]
// x[b,p,i] = inputs[b, i/256, p, (i%256)/16, i%16]
//
// B=128, C=3, P=196, K1=768, N1=32, N2=64, E=768. Rows = 25088.

#define TM        32
#define NTHREADS  256

__device__ __forceinline__ unsigned long long pack2(float lo, float hi) {
    unsigned long long r;
    asm("mov.b64 %0, {%1, %2};" : "=l"(r) : "f"(lo), "f"(hi));
    return r;
}
__device__ __forceinline__ void unpack2(unsigned long long v, float& lo, float& hi) {
    asm("mov.b64 {%0, %1}, %2;" : "=f"(lo), "=f"(hi) : "l"(v));
}
// Packed fp32 pair FMA (sm_100+): d = a*b + c elementwise on 2 floats.
__device__ __forceinline__ unsigned long long ffma2(unsigned long long a,
                                                    unsigned long long b,
                                                    unsigned long long c) {
    unsigned long long d;
    asm("fma.rn.f32x2 %0, %1, %2, %3;" : "=l"(d) : "l"(a), "l"(b), "l"(c));
    return d;
}

__global__ __launch_bounds__(NTHREADS, 2)
void patch_embed_main(const float* __restrict__ X,
                      const float* __restrict__ W1, const float* __restrict__ b1,
                      const float* __restrict__ W2, const float* __restrict__ b2,
                      const float* __restrict__ W3, const float* __restrict__ b3,
                      const float* __restrict__ pos, float* __restrict__ out)
{
    extern __shared__ float sm[];
    float* xs  = sm;                 // [32][768] fp32  (98304 B) -- dead after G1
    float* h1  = sm + TM * 768;      // [32][32]        (4096 B)
    float* h2d = sm;                 // [32][128] duplicated pairs, aliases xs

    const int t  = threadIdx.x;
    const int r0 = blockIdx.x * TM;  // first global patch-row of this tile

    // ---------------- Stage 0: gather X tile into smem (transpose-aware) -------------
    // Tile = 32 rows x 768 floats = 6144 float4, 24 per thread. Each channel segment
    // of a patch is 256 contiguous floats in gmem -> coalesced float4 loads.
#pragma unroll
    for (int it = 0; it < 24; ++it) {
        int f   = it * NTHREADS + t;     // float4 id in tile
        int m   = f / 192;               // row within tile (768/4 = 192 f4 per row)
        int j   = f - m * 192;
        int i   = j * 4;                 // element index within 768
        int c   = i >> 8;                // channel
        int rem = i & 255;               // h*16+w
        int r   = r0 + m;
        int b   = r / 196;
        int p   = r - b * 196;
        float4 v = __ldg((const float4*)(X + ((((size_t)b * 3 + c) * 196 + p) << 8) + rem));
        *(float4*)(xs + m * 768 + i) = v;
    }
    __syncthreads();

    // ---------------- G1: H1[32][32] = Xtile @ W1 + b1 --------------------------------
    // Thread: 1 row x 4 cols. W1 row slice loaded as ulonglong2 (LDG.128 -> two f32x2
    // operands, zero pack cost). x broadcast pays one pack per k.
    {
        const int np = t & 7;            // 8 col-groups of 4
        const int m  = t >> 3;           // 32 rows
        const int n0 = np * 4;
        unsigned long long acc0 = 0ull, acc1 = 0ull;
        const float* xrow = xs + m * 768;
#pragma unroll 8
        for (int k = 0; k < 768; ++k) {
            float xv = xrow[k];
            unsigned long long xp = pack2(xv, xv);
            ulonglong2 w = __ldg((const ulonglong2*)(W1 + k * 32 + n0));
            acc0 = ffma2(xp, w.x, acc0);
            acc1 = ffma2(xp, w.y, acc1);
        }
        float a0, a1, a2, a3;
        unpack2(acc0, a0, a1);
        unpack2(acc1, a2, a3);
        float4 bb = __ldg((const float4*)(b1 + n0));
        *(float4*)(h1 + m * 32 + n0) =
            make_float4(a0 + bb.x, a1 + bb.y, a2 + bb.z, a3 + bb.w);
    }
    __syncthreads();   // h1 ready; xs dead from here on

    // ---------------- G2: H2dup[32][128] = dup(H1 @ W2 + b2) --------------------------
    // Each h2 value stored twice ((v,v) pairs) so G3's LDS.64 yields broadcast pairs.
#pragma unroll
    for (int s = 0; s < 4; ++s) {
        int idx = s * NTHREADS + t;
        int m   = idx >> 5;              // 32 rows
        int ep  = idx & 31;              // 32 e-pairs (64 cols)
        unsigned long long acc = 0ull;
        const float* hrow = h1 + m * 32;
#pragma unroll
        for (int k = 0; k < 32; ++k) {
            float hv = hrow[k];
            unsigned long long w = __ldg((const unsigned long long*)(W2 + k * 64 + ep * 2));
            acc = ffma2(pack2(hv, hv), w, acc);
        }
        float v0, v1;
        unpack2(acc, v0, v1);
        float2 bb = __ldg((const float2*)(b2 + ep * 2));
        v0 += bb.x; v1 += bb.y;
        *(float4*)(h2d + m * 128 + ep * 4) = make_float4(v0, v0, v1, v1);
    }
    __syncthreads();

    // ---------------- G3: OUT[32][768] = H2 @ W3 + b3 + pos ---------------------------
    // Thread: 8 rows x 2 e-pairs (4 cols). Per k: 8 LDS.64 (dup pairs, no MOVs)
    // + 2 LDG.64 (W3) + 16 ffma2. 3 passes cover E=768.
    {
        const int ep = t & 63;           // 64 e-pairs -> 128 cols per group
        const int mg = t >> 6;           // 4 row-groups of 8
        const int m0 = mg * 8;

        size_t obase[8];
        int    pbase[8];
#pragma unroll
        for (int j = 0; j < 8; ++j) {
            int r = r0 + m0 + j;
            int b = r / 196;
            int p = r - b * 196;
            obase[j] = ((size_t)b * 197 + p + 1) * 768;
            pbase[j] = (p + 1) * 768;
        }

#pragma unroll
        for (int pass = 0; pass < 3; ++pass) {
            const int ea = pass * 256 + ep * 2;
            const int eb = ea + 128;
            unsigned long long accA[8], accB[8];
#pragma unroll
            for (int j = 0; j < 8; ++j) { accA[j] = 0ull; accB[j] = 0ull; }

#pragma unroll 8
            for (int k = 0; k < 64; ++k) {
                unsigned long long wa = __ldg((const unsigned long long*)(W3 + k * 768 + ea));
                unsigned long long wb = __ldg((const unsigned long long*)(W3 + k * 768 + eb));
#pragma unroll
                for (int j = 0; j < 8; ++j) {
                    unsigned long long hp =
                        *(const unsigned long long*)(h2d + (m0 + j) * 128 + k * 2);
                    accA[j] = ffma2(hp, wa, accA[j]);
                    accB[j] = ffma2(hp, wb, accB[j]);
                }
            }

            float2 b3a = __ldg((const float2*)(b3 + ea));
            float2 b3b = __ldg((const float2*)(b3 + eb));
#pragma unroll
            for (int j = 0; j < 8; ++j) {
                float2 pa = __ldg((const float2*)(pos + pbase[j] + ea));
                float2 pb = __ldg((const float2*)(pos + pbase[j] + eb));
                float xa, ya, xb, yb;
                unpack2(accA[j], xa, ya);
                unpack2(accB[j], xb, yb);
                *(float2*)(out + obase[j] + ea) =
                    make_float2(xa + b3a.x + pa.x, ya + b3a.y + pa.y);
                *(float2*)(out + obase[j] + eb) =
                    make_float2(xb + b3b.x + pb.x, yb + b3b.y + pb.y);
            }
        }
    }
}

// out[b, 0, :] = cls_token + pos_enc[0]
__global__ void cls_row_kernel(const float* __restrict__ cls,
                               const float* __restrict__ pos,
                               float* __restrict__ out)
{
    int i  = blockIdx.x * blockDim.x + threadIdx.x;   // float4 index, 128*192 total
    int e4 = i % 192;
    int b  = i / 192;
    float4 c = __ldg((const float4*)cls + e4);
    float4 p = __ldg((const float4*)pos + e4);
    *((float4*)(out + (size_t)b * 197 * 768) + e4) =
        make_float4(c.x + p.x, c.y + p.y, c.z + p.z, c.w + p.w);
}

extern "C" void kernel_launch(void* const* d_in, const int* in_sizes, int n_in,
                              void* d_out, int out_size)
{
    const float* X   = (const float*)d_in[0];
    const float* W1  = (const float*)d_in[1];
    const float* b1  = (const float*)d_in[2];
    const float* W2  = (const float*)d_in[3];
    const float* b2  = (const float*)d_in[4];
    const float* W3  = (const float*)d_in[5];
    const float* b3  = (const float*)d_in[6];
    const float* cls = (const float*)d_in[7];
    const float* pos = (const float*)d_in[8];
    float* out = (float*)d_out;

    const int smem = (TM * 768 + TM * 32) * (int)sizeof(float);  // 102400 B
    cudaFuncSetAttribute(patch_embed_main,
                         cudaFuncAttributeMaxDynamicSharedMemorySize, smem);

    patch_embed_main<<<784, NTHREADS, smem>>>(X, W1, b1, W2, b2, W3, b3, pos, out);
    cls_row_kernel<<<96, 256>>>(cls, pos, out);
}

// round 2
// speedup vs baseline: 1.0048x; 1.0048x over previous
#include <cuda_runtime.h>

// PatchEmbeder: out[b,0,:] = cls + pos[0];  out[b,p+1,:] = ((x@W1+b1)@W2+b2)@W3+b3 + pos[p+1]
// x[b,p,i] = inputs[b, i/256, p, (i%256)/16, i%16]
//
// B=128, C=3, P=196, K1=768, N1=32, N2=64, E=768. Rows = 25088.

#define TM        32
#define NTHREADS  256

__device__ __forceinline__ unsigned long long pack2(float lo, float hi) {
    unsigned long long r;
    asm("mov.b64 %0, {%1, %2};" : "=l"(r) : "f"(lo), "f"(hi));
    return r;
}
__device__ __forceinline__ void unpack2(unsigned long long v, float& lo, float& hi) {
    asm("mov.b64 {%0, %1}, %2;" : "=f"(lo), "=f"(hi) : "l"(v));
}
// Packed fp32 pair FMA (sm_100+): d = a*b + c elementwise on 2 floats.
__device__ __forceinline__ unsigned long long ffma2(unsigned long long a,
                                                    unsigned long long b,
                                                    unsigned long long c) {
    unsigned long long d;
    asm("fma.rn.f32x2 %0, %1, %2, %3;" : "=l"(d) : "l"(a), "l"(b), "l"(c));
    return d;
}

__global__ __launch_bounds__(NTHREADS, 2)
void patch_embed_main(const float* __restrict__ X,
                      const float* __restrict__ W1, const float* __restrict__ b1,
                      const float* __restrict__ W2, const float* __restrict__ b2,
                      const float* __restrict__ W3, const float* __restrict__ b3,
                      const float* __restrict__ pos, float* __restrict__ out)
{
    extern __shared__ float sm[];
    float* xs  = sm;                 // [32][768] fp32  (98304 B) -- dead after G1
    float* h1  = sm + TM * 768;      // [32][32]        (4096 B)
    float* h2d = sm;                 // [32][128] duplicated pairs, aliases xs

    const int t  = threadIdx.x;
    const int r0 = blockIdx.x * TM;  // first global patch-row of this tile

    // ---------------- Stage 0: gather X tile into smem (transpose-aware) -------------
    // Tile = 32 rows x 768 floats = 6144 float4, 24 per thread. Each channel segment
    // of a patch is 256 contiguous floats in gmem -> coalesced float4 loads.
#pragma unroll
    for (int it = 0; it < 24; ++it) {
        int f   = it * NTHREADS + t;     // float4 id in tile
        int m   = f / 192;               // row within tile (768/4 = 192 f4 per row)
        int j   = f - m * 192;
        int i   = j * 4;                 // element index within 768
        int c   = i >> 8;                // channel
        int rem = i & 255;               // h*16+w
        int r   = r0 + m;
        int b   = r / 196;
        int p   = r - b * 196;
        float4 v = __ldg((const float4*)(X + ((((size_t)b * 3 + c) * 196 + p) << 8) + rem));
        *(float4*)(xs + m * 768 + i) = v;
    }
    __syncthreads();

    // ---------------- G1: H1[32][32] = Xtile @ W1 + b1 --------------------------------
    // Thread: 1 row x 4 cols. W1 row slice loaded as ulonglong2 (LDG.128 -> two f32x2
    // operands, zero pack cost). x broadcast pays one pack per k.
    {
        const int np = t & 7;            // 8 col-groups of 4
        const int m  = t >> 3;           // 32 rows
        const int n0 = np * 4;
        unsigned long long acc0 = 0ull, acc1 = 0ull;
        const float* xrow = xs + m * 768;
#pragma unroll 8
        for (int k = 0; k < 768; ++k) {
            float xv = xrow[k];
            unsigned long long xp = pack2(xv, xv);
            ulonglong2 w = __ldg((const ulonglong2*)(W1 + k * 32 + n0));
            acc0 = ffma2(xp, w.x, acc0);
            acc1 = ffma2(xp, w.y, acc1);
        }
        float a0, a1, a2, a3;
        unpack2(acc0, a0, a1);
        unpack2(acc1, a2, a3);
        float4 bb = __ldg((const float4*)(b1 + n0));
        *(float4*)(h1 + m * 32 + n0) =
            make_float4(a0 + bb.x, a1 + bb.y, a2 + bb.z, a3 + bb.w);
    }
    __syncthreads();   // h1 ready; xs dead from here on

    // ---------------- G2: H2dup[32][128] = dup(H1 @ W2 + b2) --------------------------
    // Each h2 value stored twice ((v,v) pairs) so G3's LDS.64 yields broadcast pairs.
#pragma unroll
    for (int s = 0; s < 4; ++s) {
        int idx = s * NTHREADS + t;
        int m   = idx >> 5;              // 32 rows
        int ep  = idx & 31;              // 32 e-pairs (64 cols)
        unsigned long long acc = 0ull;
        const float* hrow = h1 + m * 32;
#pragma unroll
        for (int k = 0; k < 32; ++k) {
            float hv = hrow[k];
            unsigned long long w = __ldg((const unsigned long long*)(W2 + k * 64 + ep * 2));
            acc = ffma2(pack2(hv, hv), w, acc);
        }
        float v0, v1;
        unpack2(acc, v0, v1);
        float2 bb = __ldg((const float2*)(b2 + ep * 2));
        v0 += bb.x; v1 += bb.y;
        *(float4*)(h2d + m * 128 + ep * 4) = make_float4(v0, v0, v1, v1);
    }
    __syncthreads();

    // ---------------- G3: OUT[32][768] = H2 @ W3 + b3 + pos ---------------------------
    // Thread: 8 rows x 2 e-pairs (4 cols). Per k: 8 LDS.64 (dup pairs, no MOVs)
    // + 2 LDG.64 (W3) + 16 ffma2. 3 passes cover E=768.
    {
        const int ep = t & 63;           // 64 e-pairs -> 128 cols per group
        const int mg = t >> 6;           // 4 row-groups of 8
        const int m0 = mg * 8;

        size_t obase[8];
        int    pbase[8];
#pragma unroll
        for (int j = 0; j < 8; ++j) {
            int r = r0 + m0 + j;
            int b = r / 196;
            int p = r - b * 196;
            obase[j] = ((size_t)b * 197 + p + 1) * 768;
            pbase[j] = (p + 1) * 768;
        }

#pragma unroll
        for (int pass = 0; pass < 3; ++pass) {
            const int ea = pass * 256 + ep * 2;
            const int eb = ea + 128;
            unsigned long long accA[8], accB[8];
#pragma unroll
            for (int j = 0; j < 8; ++j) { accA[j] = 0ull; accB[j] = 0ull; }

#pragma unroll 8
            for (int k = 0; k < 64; ++k) {
                unsigned long long wa = __ldg((const unsigned long long*)(W3 + k * 768 + ea));
                unsigned long long wb = __ldg((const unsigned long long*)(W3 + k * 768 + eb));
#pragma unroll
                for (int j = 0; j < 8; ++j) {
                    unsigned long long hp =
                        *(const unsigned long long*)(h2d + (m0 + j) * 128 + k * 2);
                    accA[j] = ffma2(hp, wa, accA[j]);
                    accB[j] = ffma2(hp, wb, accB[j]);
                }
            }

            float2 b3a = __ldg((const float2*)(b3 + ea));
            float2 b3b = __ldg((const float2*)(b3 + eb));
#pragma unroll
            for (int j = 0; j < 8; ++j) {
                float2 pa = __ldg((const float2*)(pos + pbase[j] + ea));
                float2 pb = __ldg((const float2*)(pos + pbase[j] + eb));
                float xa, ya, xb, yb;
                unpack2(accA[j], xa, ya);
                unpack2(accB[j], xb, yb);
                *(float2*)(out + obase[j] + ea) =
                    make_float2(xa + b3a.x + pa.x, ya + b3a.y + pa.y);
                *(float2*)(out + obase[j] + eb) =
                    make_float2(xb + b3b.x + pb.x, yb + b3b.y + pb.y);
            }
        }
    }
}

// out[b, 0, :] = cls_token + pos_enc[0]
__global__ void cls_row_kernel(const float* __restrict__ cls,
                               const float* __restrict__ pos,
                               float* __restrict__ out)
{
    int i  = blockIdx.x * blockDim.x + threadIdx.x;   // float4 index, 128*192 total
    int e4 = i % 192;
    int b  = i / 192;
    float4 c = __ldg((const float4*)cls + e4);
    float4 p = __ldg((const float4*)pos + e4);
    *((float4*)(out + (size_t)b * 197 * 768) + e4) =
        make_float4(c.x + p.x, c.y + p.y, c.z + p.z, c.w + p.w);
}

extern "C" void kernel_launch(void* const* d_in, const int* in_sizes, int n_in,
                              void* d_out, int out_size)
{
    const float* X   = (const float*)d_in[0];
    const float* W1  = (const float*)d_in[1];
    const float* b1  = (const float*)d_in[2];
    const float* W2  = (const float*)d_in[3];
    const float* b2  = (const float*)d_in[4];
    const float* W3  = (const float*)d_in[5];
    const float* b3  = (const float*)d_in[6];
    const float* cls = (const float*)d_in[7];
    const float* pos = (const float*)d_in[8];
    float* out = (float*)d_out;

    const int smem = (TM * 768 + TM * 32) * (int)sizeof(float);  // 102400 B
    cudaFuncSetAttribute(patch_embed_main,
                         cudaFuncAttributeMaxDynamicSharedMemorySize, smem);

    patch_embed_main<<<784, NTHREADS, smem>>>(X, W1, b1, W2, b2, W3, b3, pos, out);
    cls_row_kernel<<<96, 256>>>(cls, pos, out);
}

// round 4
// speedup vs baseline: 1.4762x; 1.4692x over previous
#include <cuda_runtime.h>
#include <cuda_bf16.h>
#include <cstdint>

// PatchEmbeder via mma.sync bf16 (split hi/lo) + affine collapse.
// out[b,0,:]   = cls + pos[0]                                  (prep kernel)
// out[b,p+1,:] = x_patch @ W1 @ (W2@W3) + beff + pos[p+1]      (main kernel)
// x[b,p,k] = inputs[b, k/256, p, (k%256)/16, k%16]
// B=128, P=196 -> 25088 rows = 196 CTAs x 128 rows. K1=768, N1=32(=K2), E=768.

#define THREADS 256

// ---- device scratch (rebuilt every replay by prep_kernel) ----
// Fragment-layout weights for mma.sync m16n8k16 (B operand, col-major frag):
//   uint4 per (fragment, lane): {b0_hi, b1_hi, b0_lo, b1_lo}
__device__ __align__(16) uint4 g_W1F [6 * 8 * 4 * 32];  // [k-tile 48][n-tile 4][lane]
__device__ __align__(16) uint4 g_W23F[96 * 2 * 32];     // [n-tile 96][k-tile 2][lane]
__device__ __align__(16) float g_beff[768];

__device__ __forceinline__ uint32_t bf2bits(__nv_bfloat162 v) {
    return *reinterpret_cast<uint32_t*>(&v);
}
__device__ __forceinline__ void split2(float a, float b, uint32_t& h, uint32_t& l) {
    __nv_bfloat162 H = __floats2bfloat162_rn(a, b);
    float ha = __bfloat162float(H.x), hb = __bfloat162float(H.y);
    __nv_bfloat162 L = __floats2bfloat162_rn(a - ha, b - hb);
    h = bf2bits(H); l = bf2bits(L);
}

// D += A(bf16 16x16) * B(bf16 16x8), fp32 accumulate. Non-volatile: let ptxas schedule.
__device__ __forceinline__ void mma16816(float& c0, float& c1, float& c2, float& c3,
                                         const uint32_t a[4], uint32_t b0, uint32_t b1) {
    asm("mma.sync.aligned.m16n8k16.row.col.f32.bf16.bf16.f32 "
        "{%0,%1,%2,%3}, {%4,%5,%6,%7}, {%8,%9}, {%0,%1,%2,%3};"
        : "+f"(c0), "+f"(c1), "+f"(c2), "+f"(c3)
        : "r"(a[0]), "r"(a[1]), "r"(a[2]), "r"(a[3]), "r"(b0), "r"(b1));
}
__device__ __forceinline__ void ldsm4(uint32_t r[4], uint32_t addr) {
    asm volatile("ldmatrix.sync.aligned.m8n8.x4.shared.b16 {%0,%1,%2,%3}, [%4];"
                 : "=r"(r[0]), "=r"(r[1]), "=r"(r[2]), "=r"(r[3]) : "r"(addr));
}
__device__ __forceinline__ uint32_t smem_u32(const void* p) {
    uint32_t a;
    asm("{ .reg .u64 t; cvta.to.shared.u64 t, %1; cvt.u32.u64 %0, t; }" : "=r"(a) : "l"(p));
    return a;
}

// =====================================================================
// prep: bake W1 / W23=W2@W3 into mma fragment layout (hi/lo), beff, cls rows.
// grid 96 x 256 = 24576 threads.
// =====================================================================
__global__ void prep_kernel(const float* __restrict__ W1, const float* __restrict__ b1,
                            const float* __restrict__ W2, const float* __restrict__ b2,
                            const float* __restrict__ W3, const float* __restrict__ b3,
                            const float* __restrict__ cls, const float* __restrict__ pos,
                            float* __restrict__ out)
{
    const int g = blockIdx.x * 256 + threadIdx.x;   // 0..24575

    // ---- W1 fragments: element (k = g>>5 in 0..767, n = g&31) ----
    {
        const int k = g >> 5, n = g & 31;
        const float v = __ldg(W1 + k * 32 + n);
        const __nv_bfloat16 h = __float2bfloat16(v);
        const __nv_bfloat16 l = __float2bfloat16(v - __bfloat162float(h));
        const int kt = k >> 4, kin = k & 15;
        const int lane = ((n & 7) << 2) + ((kin & 7) >> 1);
        const int reg = kin >> 3, half = kin & 1;
        uint16_t* base = (uint16_t*)&g_W1F[((kt << 2) + (n >> 3)) * 32 + lane];
        base[(reg << 1) + half]     = *(const uint16_t*)&h;
        base[4 + (reg << 1) + half] = *(const uint16_t*)&l;
    }
    // ---- W23 fragments: element (e = g>>5, k2 = g&31); W23[k2][e] = W2[k2,:]·W3[:,e]
    {
        const int e = g >> 5, k2 = g & 31;
        float acc = 0.f;
#pragma unroll 16
        for (int j = 0; j < 64; ++j)
            acc += __ldg(W2 + k2 * 64 + j) * __ldg(W3 + j * 768 + e);
        const __nv_bfloat16 h = __float2bfloat16(acc);
        const __nv_bfloat16 l = __float2bfloat16(acc - __bfloat162float(h));
        const int kt = k2 >> 4, kin = k2 & 15;
        const int lane = ((e & 7) << 2) + ((kin & 7) >> 1);
        const int reg = kin >> 3, half = kin & 1;
        uint16_t* base = (uint16_t*)&g_W23F[(((e >> 3) << 1) + kt) * 32 + lane];
        base[(reg << 1) + half]     = *(const uint16_t*)&h;
        base[4 + (reg << 1) + half] = *(const uint16_t*)&l;
    }
    // ---- beff[e] = b3[e] + sum_j (b2[j] + b1·W2[:,j]) * W3[j][e] ----
    if (g < 768) {
        float acc = __ldg(b3 + g);
        for (int j = 0; j < 64; ++j) {
            float t1 = __ldg(b2 + j);
#pragma unroll 8
            for (int i = 0; i < 32; ++i) t1 += __ldg(b1 + i) * __ldg(W2 + i * 64 + j);
            acc += t1 * __ldg(W3 + j * 768 + g);
        }
        g_beff[g] = acc;
    }
    // ---- cls rows: out[b][0][:] = cls + pos[0]  (128 b x 192 float4) ----
    {
        const int e4 = g % 192, b = g / 192;
        const float4 c = __ldg((const float4*)cls + e4);
        const float4 pp = __ldg((const float4*)pos + e4);
        *((float4*)(out + (size_t)b * 197 * 768) + e4) =
            make_float4(c.x + pp.x, c.y + pp.y, c.z + pp.z, c.w + pp.w);
    }
}

// =====================================================================
// main: 196 CTAs x 256 threads, 128 rows each. 64 KB smem X-stage buffer.
// Smem row layout: row r at r*512: [hi 256B | lo 256B], 16B groups swizzled
// by g' = g ^ (r&7) for conflict-free ldmatrix.
// =====================================================================
__global__ __launch_bounds__(THREADS, 2)
void patch_embed_mma(const float* __restrict__ X, const float* __restrict__ pos,
                     float* __restrict__ out)
{
    extern __shared__ char smem[];
    const uint32_t sb = smem_u32(smem);
    const int t = threadIdx.x;
    const int w = t >> 5;
    const int ln = t & 31;
    const int r0 = blockIdx.x * 128;
    const int wr0 = w << 4;            // warp's first row (16 rows per warp)

    // ---------------- G1: H[128x32] = X @ W1, fp32 accum in fragments -------------
    float acc1[4][4];
#pragma unroll
    for (int i = 0; i < 4; ++i)
#pragma unroll
        for (int j = 0; j < 4; ++j) acc1[i][j] = 0.f;

    // precompute ldmatrix lane address pieces
    const int m  = ln >> 3;                           // matrix index 0..3
    const int rrl = wr0 + (ln & 7) + ((m & 1) << 3);  // row this lane points at
    const uint32_t lane_rowbase = sb + rrl * 512;
    const int ggm = m >> 1;                           // +0 or +1 group (k low/high 8)

    for (int kc = 0; kc < 6; ++kc) {
        if (kc) __syncthreads();                      // protect buffer from prev consume
        // ---- stage chunk kc: 128 rows x 128 k (channel kc/2, rem (kc&1)*128) ----
        const int ch = kc >> 1;
        const int rem0 = (kc & 1) << 7;
        const int kk = ln << 2;                       // this lane's 4 k-values
        const int gsw = ln >> 1;                      // 16B group = k/8
        const int off8 = (ln & 1) << 3;
#pragma unroll
        for (int it = 0; it < 16; ++it) {
            const int r = (it << 3) + w;              // warp stages one row per it
            const int R = r0 + r;
            const int b = R / 196;
            const int p = R - b * 196;
            const float4 v = __ldg((const float4*)(
                X + (((size_t)(b * 3 + ch) * 196 + p) << 8) + rem0 + kk));
            __nv_bfloat162 h01 = __floats2bfloat162_rn(v.x, v.y);
            __nv_bfloat162 h23 = __floats2bfloat162_rn(v.z, v.w);
            __nv_bfloat162 l01 = __floats2bfloat162_rn(v.x - __bfloat162float(h01.x),
                                                       v.y - __bfloat162float(h01.y));
            __nv_bfloat162 l23 = __floats2bfloat162_rn(v.z - __bfloat162float(h23.x),
                                                       v.w - __bfloat162float(h23.y));
            const uint32_t base = r * 512 + ((uint32_t)(gsw ^ (r & 7)) << 4) + off8;
            *(uint2*)(smem + base)       = make_uint2(bf2bits(h01), bf2bits(h23));
            *(uint2*)(smem + base + 256) = make_uint2(bf2bits(l01), bf2bits(l23));
        }
        __syncthreads();

        // ---- consume: 8 k-tiles of 16 ----
#pragma unroll
        for (int kt = 0; kt < 8; ++kt) {
            const int gg = (kt << 1) + ggm;
            const uint32_t ahaddr = lane_rowbase + ((uint32_t)(gg ^ (rrl & 7)) << 4);
            uint32_t ah[4], al[4];
            ldsm4(ah, ahaddr);
            ldsm4(al, ahaddr + 256);
            const uint4* bp = &g_W1F[(((kc << 3) + kt) << 2) * 32 + ln];
#pragma unroll
            for (int nt = 0; nt < 4; ++nt) {
                const uint4 bf = __ldg(bp + nt * 32);
                mma16816(acc1[nt][0], acc1[nt][1], acc1[nt][2], acc1[nt][3], ah, bf.x, bf.y);
                mma16816(acc1[nt][0], acc1[nt][1], acc1[nt][2], acc1[nt][3], ah, bf.z, bf.w);
                mma16816(acc1[nt][0], acc1[nt][1], acc1[nt][2], acc1[nt][3], al, bf.x, bf.y);
            }
        }
    }

    // ---------------- H fragments -> G23 A fragments (thread-local remap) ----------
    // A(16x16, k-tile q) regs: a0=(r, k<8)=nt(2q).c01  a1=(r+8,k<8)=nt(2q).c23
    //                          a2=(r, k>=8)=nt(2q+1).c01  a3=(r+8,k>=8)=nt(2q+1).c23
    uint32_t Ah[2][4], Al[2][4];
#pragma unroll
    for (int q = 0; q < 2; ++q) {
        split2(acc1[2*q][0],   acc1[2*q][1],   Ah[q][0], Al[q][0]);
        split2(acc1[2*q][2],   acc1[2*q][3],   Ah[q][1], Al[q][1]);
        split2(acc1[2*q+1][0], acc1[2*q+1][1], Ah[q][2], Al[q][2]);
        split2(acc1[2*q+1][2], acc1[2*q+1][3], Ah[q][3], Al[q][3]);
    }

    // ---------------- G23: out rows = H @ W23 + beff + pos, fused epilogue ---------
    const int rA = r0 + wr0 + (ln >> 2);
    const int bA = rA / 196, pA = rA - bA * 196;
    const int rB = rA + 8;
    const int bB = rB / 196, pB = rB - bB * 196;
    float* const orowA = out + ((size_t)bA * 197 + pA + 1) * 768;
    float* const orowB = out + ((size_t)bB * 197 + pB + 1) * 768;
    const float* const prowA = pos + (pA + 1) * 768;
    const float* const prowB = pos + (pB + 1) * 768;
    const int ncol = (ln & 3) << 1;

#pragma unroll 4
    for (int nt = 0; nt < 96; ++nt) {
        const uint4 b0 = __ldg(&g_W23F[((nt << 1) + 0) * 32 + ln]);
        const uint4 b1 = __ldg(&g_W23F[((nt << 1) + 1) * 32 + ln]);
        float c0 = 0.f, c1 = 0.f, c2 = 0.f, c3 = 0.f;
        mma16816(c0, c1, c2, c3, Ah[0], b0.x, b0.y);
        mma16816(c0, c1, c2, c3, Ah[0], b0.z, b0.w);
        mma16816(c0, c1, c2, c3, Al[0], b0.x, b0.y);
        mma16816(c0, c1, c2, c3, Ah[1], b1.x, b1.y);
        mma16816(c0, c1, c2, c3, Ah[1], b1.z, b1.w);
        mma16816(c0, c1, c2, c3, Al[1], b1.x, b1.y);

        const int n = (nt << 3) + ncol;
        const float2 be = __ldg((const float2*)(g_beff + n));
        const float2 pa = __ldg((const float2*)(prowA + n));
        const float2 pb = __ldg((const float2*)(prowB + n));
        *(float2*)(orowA + n) = make_float2(c0 + be.x + pa.x, c1 + be.y + pa.y);
        *(float2*)(orowB + n) = make_float2(c2 + be.x + pb.x, c3 + be.y + pb.y);
    }
}

extern "C" void kernel_launch(void* const* d_in, const int* in_sizes, int n_in,
                              void* d_out, int out_size)
{
    const float* X   = (const float*)d_in[0];
    const float* W1  = (const float*)d_in[1];
    const float* b1  = (const float*)d_in[2];
    const float* W2  = (const float*)d_in[3];
    const float* b2  = (const float*)d_in[4];
    const float* W3  = (const float*)d_in[5];
    const float* b3  = (const float*)d_in[6];
    const float* cls = (const float*)d_in[7];
    const float* pos = (const float*)d_in[8];
    float* out = (float*)d_out;

    const int smem = 65536;   // 128 rows x 512 B (bf16 hi|lo planes)
    cudaFuncSetAttribute(patch_embed_mma,
                         cudaFuncAttributeMaxDynamicSharedMemorySize, smem);

    prep_kernel<<<96, 256>>>(W1, b1, W2, b2, W3, b3, cls, pos, out);
    patch_embed_mma<<<196, THREADS, smem>>>(X, pos, out);
}

// round 5
// speedup vs baseline: 2.6137x; 1.7705x over previous
#include <cuda_runtime.h>
#include <cuda_bf16.h>
#include <cstdint>

// PatchEmbeder via mma.sync bf16 (split hi/lo) + affine collapse.
// out[b,0,:]   = cls + pos[0]                                  (prep kernel)
// out[b,p+1,:] = x_patch @ W1 @ (W2@W3) + beff + pos[p+1]      (main kernel)
// x[b,p,k] = inputs[b, k/256, p, (k%256)/16, k%16]
// B=128, P=196 -> 25088 rows = 392 CTAs x 64 rows. K1=768, N1=32(=K2), E=768.

#define THREADS 128

// ---- device scratch (rebuilt every replay by prep_kernel) ----
// Fragment-layout weights for mma.sync m16n8k16 (B operand, col-major frag):
//   uint4 per (fragment, lane): {b0_hi, b1_hi, b0_lo, b1_lo}
__device__ __align__(16) uint4 g_W1F [6 * 8 * 4 * 32];  // [k-tile 48][n-tile 4][lane]
__device__ __align__(16) uint4 g_W23F[96 * 2 * 32];     // [n-tile 96][k-tile 2][lane]
__device__ __align__(16) float g_beff[768];

__device__ __forceinline__ uint32_t bf2bits(__nv_bfloat162 v) {
    return *reinterpret_cast<uint32_t*>(&v);
}
__device__ __forceinline__ void split2(float a, float b, uint32_t& h, uint32_t& l) {
    __nv_bfloat162 H = __floats2bfloat162_rn(a, b);
    float ha = __bfloat162float(H.x), hb = __bfloat162float(H.y);
    __nv_bfloat162 L = __floats2bfloat162_rn(a - ha, b - hb);
    h = bf2bits(H); l = bf2bits(L);
}

__device__ __forceinline__ void mma16816(float& c0, float& c1, float& c2, float& c3,
                                         const uint32_t a[4], uint32_t b0, uint32_t b1) {
    asm("mma.sync.aligned.m16n8k16.row.col.f32.bf16.bf16.f32 "
        "{%0,%1,%2,%3}, {%4,%5,%6,%7}, {%8,%9}, {%0,%1,%2,%3};"
        : "+f"(c0), "+f"(c1), "+f"(c2), "+f"(c3)
        : "r"(a[0]), "r"(a[1]), "r"(a[2]), "r"(a[3]), "r"(b0), "r"(b1));
}
__device__ __forceinline__ void ldsm4(uint32_t r[4], uint32_t addr) {
    asm volatile("ldmatrix.sync.aligned.m8n8.x4.shared.b16 {%0,%1,%2,%3}, [%4];"
                 : "=r"(r[0]), "=r"(r[1]), "=r"(r[2]), "=r"(r[3]) : "r"(addr));
}
__device__ __forceinline__ uint32_t smem_u32(const void* p) {
    uint32_t a;
    asm("{ .reg .u64 t; cvta.to.shared.u64 t, %1; cvt.u32.u64 %0, t; }" : "=r"(a) : "l"(p));
    return a;
}

// =====================================================================
// prep: bake W1 / W23=W2@W3 fragments (hi/lo), beff, cls rows.
// grid 96 x 256 = 24576 threads. W2 staged in smem (stride 65: conflict-free),
// t1[j] = b2[j] + b1·W2[:,j] computed once per block; beff folded into the
// W23 loop (k2==0 lane reuses the same broadcast W3 load).
// =====================================================================
__global__ void prep_kernel(const float* __restrict__ W1, const float* __restrict__ b1,
                            const float* __restrict__ W2, const float* __restrict__ b2,
                            const float* __restrict__ W3, const float* __restrict__ b3,
                            const float* __restrict__ cls, const float* __restrict__ pos,
                            float* __restrict__ out)
{
    __shared__ float W2s[32 * 65];   // padded stride 65
    __shared__ float t1s[64];

    const int t = threadIdx.x;
    const int g = blockIdx.x * 256 + t;   // 0..24575

    // stage W2 -> smem (coalesced gmem read, padded write)
#pragma unroll
    for (int i = t; i < 2048; i += 256)
        W2s[(i >> 6) * 65 + (i & 63)] = __ldg(W2 + i);
    __syncthreads();

    // t1[j] = b2[j] + sum_i b1[i] * W2[i][j]
    if (t < 64) {
        float acc = __ldg(b2 + t);
#pragma unroll
        for (int i = 0; i < 32; ++i) acc += __ldg(b1 + i) * W2s[i * 65 + t];
        t1s[t] = acc;
    }
    __syncthreads();

    // ---- W1 fragments: element (k = g>>5 in 0..767, n = g&31) ----
    {
        const int k = g >> 5, n = g & 31;
        const float v = __ldg(W1 + k * 32 + n);
        const __nv_bfloat16 h = __float2bfloat16(v);
        const __nv_bfloat16 l = __float2bfloat16(v - __bfloat162float(h));
        const int kt = k >> 4, kin = k & 15;
        const int lane = ((n & 7) << 2) + ((kin & 7) >> 1);
        const int reg = kin >> 3, half = kin & 1;
        uint16_t* base = (uint16_t*)&g_W1F[((kt << 2) + (n >> 3)) * 32 + lane];
        base[(reg << 1) + half]     = *(const uint16_t*)&h;
        base[4 + (reg << 1) + half] = *(const uint16_t*)&l;
    }
    // ---- W23 fragments + beff: (e = g>>5, k2 = g&31) ----
    {
        const int e = g >> 5, k2 = g & 31;
        float acc = 0.f;
        float accb = (k2 == 0) ? __ldg(b3 + e) : 0.f;
#pragma unroll 16
        for (int j = 0; j < 64; ++j) {
            const float w3v = __ldg(W3 + j * 768 + e);   // warp-uniform broadcast
            acc += W2s[k2 * 65 + j] * w3v;
            if (k2 == 0) accb += t1s[j] * w3v;
        }
        const __nv_bfloat16 h = __float2bfloat16(acc);
        const __nv_bfloat16 l = __float2bfloat16(acc - __bfloat162float(h));
        const int kt = k2 >> 4, kin = k2 & 15;
        const int lane = ((e & 7) << 2) + ((kin & 7) >> 1);
        const int reg = kin >> 3, half = kin & 1;
        uint16_t* base = (uint16_t*)&g_W23F[(((e >> 3) << 1) + kt) * 32 + lane];
        base[(reg << 1) + half]     = *(const uint16_t*)&h;
        base[4 + (reg << 1) + half] = *(const uint16_t*)&l;
        if (k2 == 0) g_beff[e] = accb;
    }
    // ---- cls rows: out[b][0][:] = cls + pos[0]  (128 b x 192 float4) ----
    {
        const int e4 = g % 192, b = g / 192;
        const float4 c = __ldg((const float4*)cls + e4);
        const float4 pp = __ldg((const float4*)pos + e4);
        *((float4*)(out + (size_t)b * 197 * 768) + e4) =
            make_float4(c.x + pp.x, c.y + pp.y, c.z + pp.z, c.w + pp.w);
    }
}

// =====================================================================
// main: 392 CTAs x 128 threads (4 warps), 64 rows each. 32 KB smem stage.
// Smem row layout: row r at r*512: [hi 256B | lo 256B], 16B groups swizzled
// by g' = g ^ (r&7) for conflict-free ldmatrix.
// =====================================================================
__global__ __launch_bounds__(THREADS, 4)
void patch_embed_mma(const float* __restrict__ X, const float* __restrict__ pos,
                     float* __restrict__ out)
{
    extern __shared__ char smem[];
    const uint32_t sb = smem_u32(smem);
    const int t = threadIdx.x;
    const int w = t >> 5;              // 4 warps
    const int ln = t & 31;
    const int r0 = blockIdx.x * 64;
    const int wr0 = w << 4;            // warp's first row (16 rows per warp)

    // ---------------- G1: H[64x32] = X @ W1, fp32 accum in fragments -------------
    float acc1[4][4];
#pragma unroll
    for (int i = 0; i < 4; ++i)
#pragma unroll
        for (int j = 0; j < 4; ++j) acc1[i][j] = 0.f;

    const int m  = ln >> 3;                           // ldmatrix matrix index 0..3
    const int rrl = wr0 + (ln & 7) + ((m & 1) << 3);  // row this lane points at
    const uint32_t lane_rowbase = sb + rrl * 512;
    const int ggm = m >> 1;                           // k low/high 8 group

    for (int kc = 0; kc < 6; ++kc) {
        if (kc) __syncthreads();
        // ---- stage chunk kc: 64 rows x 128 k (channel kc/2, rem (kc&1)*128) ----
        const int ch = kc >> 1;
        const int rem0 = (kc & 1) << 7;
        const int kk = ln << 2;                       // lane's 4 k-values
        const int gsw = ln >> 1;                      // 16B group = k/8
        const int off8 = (ln & 1) << 3;
#pragma unroll
        for (int it = 0; it < 16; ++it) {
            const int r = (it << 2) + w;              // rows 0..63, one per warp per it
            const int R = r0 + r;
            const int b = R / 196;
            const int p = R - b * 196;
            const float4 v = __ldg((const float4*)(
                X + (((size_t)(b * 3 + ch) * 196 + p) << 8) + rem0 + kk));
            __nv_bfloat162 h01 = __floats2bfloat162_rn(v.x, v.y);
            __nv_bfloat162 h23 = __floats2bfloat162_rn(v.z, v.w);
            __nv_bfloat162 l01 = __floats2bfloat162_rn(v.x - __bfloat162float(h01.x),
                                                       v.y - __bfloat162float(h01.y));
            __nv_bfloat162 l23 = __floats2bfloat162_rn(v.z - __bfloat162float(h23.x),
                                                       v.w - __bfloat162float(h23.y));
            const uint32_t base = r * 512 + ((uint32_t)(gsw ^ (r & 7)) << 4) + off8;
            *(uint2*)(smem + base)       = make_uint2(bf2bits(h01), bf2bits(h23));
            *(uint2*)(smem + base + 256) = make_uint2(bf2bits(l01), bf2bits(l23));
        }
        __syncthreads();

        // ---- consume: 8 k-tiles of 16 ----
#pragma unroll
        for (int kt = 0; kt < 8; ++kt) {
            const int gg = (kt << 1) + ggm;
            const uint32_t ahaddr = lane_rowbase + ((uint32_t)(gg ^ (rrl & 7)) << 4);
            uint32_t ah[4], al[4];
            ldsm4(ah, ahaddr);
            ldsm4(al, ahaddr + 256);
            const uint4* bp = &g_W1F[(((kc << 3) + kt) << 2) * 32 + ln];
#pragma unroll
            for (int nt = 0; nt < 4; ++nt) {
                const uint4 bf = __ldg(bp + nt * 32);
                mma16816(acc1[nt][0], acc1[nt][1], acc1[nt][2], acc1[nt][3], ah, bf.x, bf.y);
                mma16816(acc1[nt][0], acc1[nt][1], acc1[nt][2], acc1[nt][3], ah, bf.z, bf.w);
                mma16816(acc1[nt][0], acc1[nt][1], acc1[nt][2], acc1[nt][3], al, bf.x, bf.y);
            }
        }
    }

    // ---------------- H fragments -> G23 A fragments (thread-local remap) ----------
    uint32_t Ah[2][4], Al[2][4];
#pragma unroll
    for (int q = 0; q < 2; ++q) {
        split2(acc1[2*q][0],   acc1[2*q][1],   Ah[q][0], Al[q][0]);
        split2(acc1[2*q][2],   acc1[2*q][3],   Ah[q][1], Al[q][1]);
        split2(acc1[2*q+1][0], acc1[2*q+1][1], Ah[q][2], Al[q][2]);
        split2(acc1[2*q+1][2], acc1[2*q+1][3], Ah[q][3], Al[q][3]);
    }

    // ---------------- G23: out rows = H @ W23 + beff + pos, fused epilogue ---------
    const int rA = r0 + wr0 + (ln >> 2);
    const int bA = rA / 196, pA = rA - bA * 196;
    const int rB = rA + 8;
    const int bB = rB / 196, pB = rB - bB * 196;
    float* const orowA = out + ((size_t)bA * 197 + pA + 1) * 768;
    float* const orowB = out + ((size_t)bB * 197 + pB + 1) * 768;
    const float* const prowA = pos + (pA + 1) * 768;
    const float* const prowB = pos + (pB + 1) * 768;
    const int ncol = (ln & 3) << 1;

#pragma unroll 4
    for (int nt = 0; nt < 96; ++nt) {
        const uint4 b0 = __ldg(&g_W23F[((nt << 1) + 0) * 32 + ln]);
        const uint4 b1 = __ldg(&g_W23F[((nt << 1) + 1) * 32 + ln]);
        float c0 = 0.f, c1 = 0.f, c2 = 0.f, c3 = 0.f;
        mma16816(c0, c1, c2, c3, Ah[0], b0.x, b0.y);
        mma16816(c0, c1, c2, c3, Ah[0], b0.z, b0.w);
        mma16816(c0, c1, c2, c3, Al[0], b0.x, b0.y);
        mma16816(c0, c1, c2, c3, Ah[1], b1.x, b1.y);
        mma16816(c0, c1, c2, c3, Ah[1], b1.z, b1.w);
        mma16816(c0, c1, c2, c3, Al[1], b1.x, b1.y);

        const int n = (nt << 3) + ncol;
        const float2 be = __ldg((const float2*)(g_beff + n));
        const float2 pa = __ldg((const float2*)(prowA + n));
        const float2 pb = __ldg((const float2*)(prowB + n));
        *(float2*)(orowA + n) = make_float2(c0 + be.x + pa.x, c1 + be.y + pa.y);
        *(float2*)(orowB + n) = make_float2(c2 + be.x + pb.x, c3 + be.y + pb.y);
    }
}

extern "C" void kernel_launch(void* const* d_in, const int* in_sizes, int n_in,
                              void* d_out, int out_size)
{
    const float* X   = (const float*)d_in[0];
    const float* W1  = (const float*)d_in[1];
    const float* b1  = (const float*)d_in[2];
    const float* W2  = (const float*)d_in[3];
    const float* b2  = (const float*)d_in[4];
    const float* W3  = (const float*)d_in[5];
    const float* b3  = (const float*)d_in[6];
    const float* cls = (const float*)d_in[7];
    const float* pos = (const float*)d_in[8];
    float* out = (float*)d_out;

    const int smem = 32768;   // 64 rows x 512 B (bf16 hi|lo planes)
    cudaFuncSetAttribute(patch_embed_mma,
                         cudaFuncAttributeMaxDynamicSharedMemorySize, smem);

    prep_kernel<<<96, 256>>>(W1, b1, W2, b2, W3, b3, cls, pos, out);
    patch_embed_mma<<<392, THREADS, smem>>>(X, pos, out);
}

// round 6
// speedup vs baseline: 2.6375x; 1.0091x over previous
#include <cuda_runtime.h>
#include <cuda_bf16.h>
#include <cstdint>

// PatchEmbeder via mma.sync bf16 (split hi/lo) + affine collapse.
// out[b,0,:]   = cls + pos[0]                                  (prep kernel)
// out[b,p+1,:] = x_patch @ W1 @ (W2@W3) + beff + pos[p+1]      (main kernel)
// x[b,p,k] = inputs[b, k/256, p, (k%256)/16, k%16]
// B=128, P=196 -> 25088 rows = 392 CTAs x 64 rows. K1=768, N1=32(=K2), E=768.

#define THREADS 128

// ---- device scratch (rebuilt every replay by prep_kernel) ----
// Fragment-layout weights for mma.sync m16n8k16 (B operand, col-major frag):
//   uint4 per (fragment, lane): {b0_hi, b1_hi, b0_lo, b1_lo}
__device__ __align__(16) uint4 g_W1F [6 * 8 * 4 * 32];  // [k-tile 48][n-tile 4][lane]
__device__ __align__(16) uint4 g_W23F[96 * 2 * 32];     // [n-tile 96][k-tile 2][lane]
__device__ __align__(16) float g_beff[768];

__device__ __forceinline__ uint32_t bf2bits(__nv_bfloat162 v) {
    return *reinterpret_cast<uint32_t*>(&v);
}
__device__ __forceinline__ void split2(float a, float b, uint32_t& h, uint32_t& l) {
    __nv_bfloat162 H = __floats2bfloat162_rn(a, b);
    float ha = __bfloat162float(H.x), hb = __bfloat162float(H.y);
    __nv_bfloat162 L = __floats2bfloat162_rn(a - ha, b - hb);
    h = bf2bits(H); l = bf2bits(L);
}

__device__ __forceinline__ void mma16816(float& c0, float& c1, float& c2, float& c3,
                                         const uint32_t a[4], uint32_t b0, uint32_t b1) {
    asm("mma.sync.aligned.m16n8k16.row.col.f32.bf16.bf16.f32 "
        "{%0,%1,%2,%3}, {%4,%5,%6,%7}, {%8,%9}, {%0,%1,%2,%3};"
        : "+f"(c0), "+f"(c1), "+f"(c2), "+f"(c3)
        : "r"(a[0]), "r"(a[1]), "r"(a[2]), "r"(a[3]), "r"(b0), "r"(b1));
}
__device__ __forceinline__ void ldsm4(uint32_t r[4], uint32_t addr) {
    asm volatile("ldmatrix.sync.aligned.m8n8.x4.shared.b16 {%0,%1,%2,%3}, [%4];"
                 : "=r"(r[0]), "=r"(r[1]), "=r"(r[2]), "=r"(r[3]) : "r"(addr));
}
__device__ __forceinline__ uint32_t smem_u32(const void* p) {
    uint32_t a;
    asm("{ .reg .u64 t; cvta.to.shared.u64 t, %1; cvt.u32.u64 %0, t; }" : "=r"(a) : "l"(p));
    return a;
}

// =====================================================================
// prep: bake W1 / W23=W2@W3 fragments (hi/lo), beff, cls rows.
// grid 96 x 256 = 24576 threads. W2 staged in smem (stride 65: conflict-free),
// t1[j] = b2[j] + b1·W2[:,j] computed once per block; beff folded into the
// W23 loop (k2==0 lane reuses the same broadcast W3 load).
// =====================================================================
__global__ void prep_kernel(const float* __restrict__ W1, const float* __restrict__ b1,
                            const float* __restrict__ W2, const float* __restrict__ b2,
                            const float* __restrict__ W3, const float* __restrict__ b3,
                            const float* __restrict__ cls, const float* __restrict__ pos,
                            float* __restrict__ out)
{
    __shared__ float W2s[32 * 65];   // padded stride 65
    __shared__ float t1s[64];

    const int t = threadIdx.x;
    const int g = blockIdx.x * 256 + t;   // 0..24575

    // stage W2 -> smem (coalesced gmem read, padded write)
#pragma unroll
    for (int i = t; i < 2048; i += 256)
        W2s[(i >> 6) * 65 + (i & 63)] = __ldg(W2 + i);
    __syncthreads();

    // t1[j] = b2[j] + sum_i b1[i] * W2[i][j]
    if (t < 64) {
        float acc = __ldg(b2 + t);
#pragma unroll
        for (int i = 0; i < 32; ++i) acc += __ldg(b1 + i) * W2s[i * 65 + t];
        t1s[t] = acc;
    }
    __syncthreads();

    // ---- W1 fragments: element (k = g>>5 in 0..767, n = g&31) ----
    {
        const int k = g >> 5, n = g & 31;
        const float v = __ldg(W1 + k * 32 + n);
        const __nv_bfloat16 h = __float2bfloat16(v);
        const __nv_bfloat16 l = __float2bfloat16(v - __bfloat162float(h));
        const int kt = k >> 4, kin = k & 15;
        const int lane = ((n & 7) << 2) + ((kin & 7) >> 1);
        const int reg = kin >> 3, half = kin & 1;
        uint16_t* base = (uint16_t*)&g_W1F[((kt << 2) + (n >> 3)) * 32 + lane];
        base[(reg << 1) + half]     = *(const uint16_t*)&h;
        base[4 + (reg << 1) + half] = *(const uint16_t*)&l;
    }
    // ---- W23 fragments + beff: (e = g>>5, k2 = g&31) ----
    {
        const int e = g >> 5, k2 = g & 31;
        float acc = 0.f;
        float accb = (k2 == 0) ? __ldg(b3 + e) : 0.f;
#pragma unroll 16
        for (int j = 0; j < 64; ++j) {
            const float w3v = __ldg(W3 + j * 768 + e);   // warp-uniform broadcast
            acc += W2s[k2 * 65 + j] * w3v;
            if (k2 == 0) accb += t1s[j] * w3v;
        }
        const __nv_bfloat16 h = __float2bfloat16(acc);
        const __nv_bfloat16 l = __float2bfloat16(acc - __bfloat162float(h));
        const int kt = k2 >> 4, kin = k2 & 15;
        const int lane = ((e & 7) << 2) + ((kin & 7) >> 1);
        const int reg = kin >> 3, half = kin & 1;
        uint16_t* base = (uint16_t*)&g_W23F[(((e >> 3) << 1) + kt) * 32 + lane];
        base[(reg << 1) + half]     = *(const uint16_t*)&h;
        base[4 + (reg << 1) + half] = *(const uint16_t*)&l;
        if (k2 == 0) g_beff[e] = accb;
    }
    // ---- cls rows: out[b][0][:] = cls + pos[0]  (128 b x 192 float4) ----
    {
        const int e4 = g % 192, b = g / 192;
        const float4 c = __ldg((const float4*)cls + e4);
        const float4 pp = __ldg((const float4*)pos + e4);
        *((float4*)(out + (size_t)b * 197 * 768) + e4) =
            make_float4(c.x + pp.x, c.y + pp.y, c.z + pp.z, c.w + pp.w);
    }
}

// =====================================================================
// main: 392 CTAs x 128 threads (4 warps), 64 rows each. 32 KB smem stage.
// Smem row layout: row r at r*512: [hi 256B | lo 256B], 16B groups swizzled
// by g' = g ^ (r&7) for conflict-free ldmatrix.
// =====================================================================
__global__ __launch_bounds__(THREADS, 4)
void patch_embed_mma(const float* __restrict__ X, const float* __restrict__ pos,
                     float* __restrict__ out)
{
    extern __shared__ char smem[];
    const uint32_t sb = smem_u32(smem);
    const int t = threadIdx.x;
    const int w = t >> 5;              // 4 warps
    const int ln = t & 31;
    const int r0 = blockIdx.x * 64;
    const int wr0 = w << 4;            // warp's first row (16 rows per warp)

    // ---------------- G1: H[64x32] = X @ W1, fp32 accum in fragments -------------
    float acc1[4][4];
#pragma unroll
    for (int i = 0; i < 4; ++i)
#pragma unroll
        for (int j = 0; j < 4; ++j) acc1[i][j] = 0.f;

    const int m  = ln >> 3;                           // ldmatrix matrix index 0..3
    const int rrl = wr0 + (ln & 7) + ((m & 1) << 3);  // row this lane points at
    const uint32_t lane_rowbase = sb + rrl * 512;
    const int ggm = m >> 1;                           // k low/high 8 group

    for (int kc = 0; kc < 6; ++kc) {
        if (kc) __syncthreads();
        // ---- stage chunk kc: 64 rows x 128 k (channel kc/2, rem (kc&1)*128) ----
        const int ch = kc >> 1;
        const int rem0 = (kc & 1) << 7;
        const int kk = ln << 2;                       // lane's 4 k-values
        const int gsw = ln >> 1;                      // 16B group = k/8
        const int off8 = (ln & 1) << 3;
#pragma unroll
        for (int it = 0; it < 16; ++it) {
            const int r = (it << 2) + w;              // rows 0..63, one per warp per it
            const int R = r0 + r;
            const int b = R / 196;
            const int p = R - b * 196;
            const float4 v = __ldg((const float4*)(
                X + (((size_t)(b * 3 + ch) * 196 + p) << 8) + rem0 + kk));
            __nv_bfloat162 h01 = __floats2bfloat162_rn(v.x, v.y);
            __nv_bfloat162 h23 = __floats2bfloat162_rn(v.z, v.w);
            __nv_bfloat162 l01 = __floats2bfloat162_rn(v.x - __bfloat162float(h01.x),
                                                       v.y - __bfloat162float(h01.y));
            __nv_bfloat162 l23 = __floats2bfloat162_rn(v.z - __bfloat162float(h23.x),
                                                       v.w - __bfloat162float(h23.y));
            const uint32_t base = r * 512 + ((uint32_t)(gsw ^ (r & 7)) << 4) + off8;
            *(uint2*)(smem + base)       = make_uint2(bf2bits(h01), bf2bits(h23));
            *(uint2*)(smem + base + 256) = make_uint2(bf2bits(l01), bf2bits(l23));
        }
        __syncthreads();

        // ---- consume: 8 k-tiles of 16; mma issued in 3 passes over nt so
        //      same-accumulator writes are separated by 4 independent mma ----
#pragma unroll
        for (int kt = 0; kt < 8; ++kt) {
            const int gg = (kt << 1) + ggm;
            const uint32_t ahaddr = lane_rowbase + ((uint32_t)(gg ^ (rrl & 7)) << 4);
            uint32_t ah[4], al[4];
            ldsm4(ah, ahaddr);
            ldsm4(al, ahaddr + 256);
            const uint4* bp = &g_W1F[(((kc << 3) + kt) << 2) * 32 + ln];
            uint4 bf[4];
#pragma unroll
            for (int nt = 0; nt < 4; ++nt) bf[nt] = __ldg(bp + nt * 32);
#pragma unroll
            for (int nt = 0; nt < 4; ++nt)
                mma16816(acc1[nt][0], acc1[nt][1], acc1[nt][2], acc1[nt][3], ah, bf[nt].x, bf[nt].y);
#pragma unroll
            for (int nt = 0; nt < 4; ++nt)
                mma16816(acc1[nt][0], acc1[nt][1], acc1[nt][2], acc1[nt][3], al, bf[nt].x, bf[nt].y);
#pragma unroll
            for (int nt = 0; nt < 4; ++nt)
                mma16816(acc1[nt][0], acc1[nt][1], acc1[nt][2], acc1[nt][3], ah, bf[nt].z, bf[nt].w);
        }
    }

    // ---------------- H fragments -> G23 A fragments (thread-local remap) ----------
    uint32_t Ah[2][4], Al[2][4];
#pragma unroll
    for (int q = 0; q < 2; ++q) {
        split2(acc1[2*q][0],   acc1[2*q][1],   Ah[q][0], Al[q][0]);
        split2(acc1[2*q][2],   acc1[2*q][3],   Ah[q][1], Al[q][1]);
        split2(acc1[2*q+1][0], acc1[2*q+1][1], Ah[q][2], Al[q][2]);
        split2(acc1[2*q+1][2], acc1[2*q+1][3], Ah[q][3], Al[q][3]);
    }

    // ---------------- G23: out rows = H @ W23 + beff + pos, fused epilogue ---------
    // 3 independent accumulator sets (hh / hl / lh terms): chains of depth 2, not 6.
    const int rA = r0 + wr0 + (ln >> 2);
    const int bA = rA / 196, pA = rA - bA * 196;
    const int rB = rA + 8;
    const int bB = rB / 196, pB = rB - bB * 196;
    float* const orowA = out + ((size_t)bA * 197 + pA + 1) * 768;
    float* const orowB = out + ((size_t)bB * 197 + pB + 1) * 768;
    const float* const prowA = pos + (pA + 1) * 768;
    const float* const prowB = pos + (pB + 1) * 768;
    const int ncol = (ln & 3) << 1;

#pragma unroll 4
    for (int nt = 0; nt < 96; ++nt) {
        const uint4 b0 = __ldg(&g_W23F[((nt << 1) + 0) * 32 + ln]);
        const uint4 b1 = __ldg(&g_W23F[((nt << 1) + 1) * 32 + ln]);
        float h0 = 0.f, h1 = 0.f, h2 = 0.f, h3 = 0.f;   // Ah*Bh
        float g0 = 0.f, g1 = 0.f, g2 = 0.f, g3 = 0.f;   // Ah*Bl
        float l0 = 0.f, l1 = 0.f, l2 = 0.f, l3 = 0.f;   // Al*Bh
        mma16816(h0, h1, h2, h3, Ah[0], b0.x, b0.y);
        mma16816(g0, g1, g2, g3, Ah[0], b0.z, b0.w);
        mma16816(l0, l1, l2, l3, Al[0], b0.x, b0.y);
        mma16816(h0, h1, h2, h3, Ah[1], b1.x, b1.y);
        mma16816(g0, g1, g2, g3, Ah[1], b1.z, b1.w);
        mma16816(l0, l1, l2, l3, Al[1], b1.x, b1.y);

        const int n = (nt << 3) + ncol;
        const float2 be = __ldg((const float2*)(g_beff + n));
        const float2 pa = __ldg((const float2*)(prowA + n));
        const float2 pb = __ldg((const float2*)(prowB + n));
        *(float2*)(orowA + n) = make_float2((h0 + g0) + (l0 + be.x + pa.x),
                                            (h1 + g1) + (l1 + be.y + pa.y));
        *(float2*)(orowB + n) = make_float2((h2 + g2) + (l2 + be.x + pb.x),
                                            (h3 + g3) + (l3 + be.y + pb.y));
    }
}

extern "C" void kernel_launch(void* const* d_in, const int* in_sizes, int n_in,
                              void* d_out, int out_size)
{
    const float* X   = (const float*)d_in[0];
    const float* W1  = (const float*)d_in[1];
    const float* b1  = (const float*)d_in[2];
    const float* W2  = (const float*)d_in[3];
    const float* b2  = (const float*)d_in[4];
    const float* W3  = (const float*)d_in[5];
    const float* b3  = (const float*)d_in[6];
    const float* cls = (const float*)d_in[7];
    const float* pos = (const float*)d_in[8];
    float* out = (float*)d_out;

    const int smem = 32768;   // 64 rows x 512 B (bf16 hi|lo planes)
    cudaFuncSetAttribute(patch_embed_mma,
                         cudaFuncAttributeMaxDynamicSharedMemorySize, smem);

    prep_kernel<<<96, 256>>>(W1, b1, W2, b2, W3, b3, cls, pos, out);
    patch_embed_mma<<<392, THREADS, smem>>>(X, pos, out);
}